// round 2
// baseline (speedup 1.0000x reference)
#include <cuda_runtime.h>

#define NN   50000
#define EE   1600000
#define DD   128
#define KK   16
#define ALPHA_F 0.05f
#define CW_F    (0.95f / 16.0f)
#define NPAD 50048   // padding so GEMM smem staging can read past node 50000 safely

// -------------------- scratch (static device globals; no allocs) ------------
__device__ float g_xA[NPAD * DD];
__device__ float g_xB[NPAD * DD];
__device__ float g_h [NPAD * DD];
__device__ int   g_deg[NN];
__device__ float g_dinv[NN];
__device__ int   g_rowptr[NN + 1];
__device__ int   g_cursor[NN];
__device__ int   g_col[EE];
__device__ float g_wn[EE];
__device__ float g_Wt[DD * DD];

// -------------------- prep kernels ------------------------------------------

// deg starts at 1 (self-loop), cursor at 0
__global__ void init_deg_kernel() {
    int v = blockIdx.x * blockDim.x + threadIdx.x;
    if (v < NN) { g_deg[v] = 1; g_cursor[v] = 0; }
}

__global__ void count_deg_kernel(const int* __restrict__ dst) {
    for (int e = blockIdx.x * blockDim.x + threadIdx.x; e < EE;
         e += gridDim.x * blockDim.x) {
        atomicAdd(&g_deg[dst[e]], 1);
    }
}

__global__ void dinv_kernel() {
    int v = blockIdx.x * blockDim.x + threadIdx.x;
    if (v < NN) g_dinv[v] = rsqrtf((float)g_deg[v]);
}

// single-block exclusive scan of (deg[v]-1) -> rowptr  (50k elems, 1024 thr)
__global__ void scan_kernel() {
    __shared__ int warp_sums[32];
    __shared__ int carry_sh;
    const int tid  = threadIdx.x;
    const int lane = tid & 31;
    const int wid  = tid >> 5;
    int carry = 0;
    for (int base = 0; base < NN; base += 1024) {
        int i = base + tid;
        int v = (i < NN) ? (g_deg[i] - 1) : 0;
        // inclusive warp scan
        int x = v;
        #pragma unroll
        for (int d = 1; d < 32; d <<= 1) {
            int y = __shfl_up_sync(0xffffffffu, x, d);
            if (lane >= d) x += y;
        }
        if (lane == 31) warp_sums[wid] = x;
        __syncthreads();
        if (wid == 0) {
            int s = warp_sums[lane];
            int t = s;
            #pragma unroll
            for (int d = 1; d < 32; d <<= 1) {
                int y = __shfl_up_sync(0xffffffffu, t, d);
                if (lane >= d) t += y;
            }
            warp_sums[lane] = t - s;   // exclusive warp offsets
        }
        __syncthreads();
        int incl = x + warp_sums[wid] + carry;
        if (i < NN) g_rowptr[i] = incl - v;   // exclusive
        __syncthreads();
        if (tid == 1023) carry_sh = incl;
        __syncthreads();
        carry = carry_sh;
    }
    if (tid == 0) g_rowptr[NN] = carry;
}

__global__ void scatter_kernel(const int* __restrict__ src,
                               const int* __restrict__ dst) {
    for (int e = blockIdx.x * blockDim.x + threadIdx.x; e < EE;
         e += gridDim.x * blockDim.x) {
        int s = src[e];
        int d = dst[e];
        int pos = g_rowptr[d] + atomicAdd(&g_cursor[d], 1);
        g_col[pos] = s;
        g_wn[pos]  = g_dinv[s] * g_dinv[d];
    }
}

__global__ void transpose_w_kernel(const float* __restrict__ W) {
    int o = threadIdx.x;    // out channel
    int i = blockIdx.x;     // in channel
    g_Wt[i * DD + o] = W[o * DD + i];
}

// h = ALPHA * x0
__global__ void hinit_kernel(const float* __restrict__ x0, float* __restrict__ h) {
    int idx = blockIdx.x * blockDim.x + threadIdx.x;      // float4 index
    const int total = NN * DD / 4;
    if (idx < total) {
        float4 v = ((const float4*)x0)[idx];
        v.x *= ALPHA_F; v.y *= ALPHA_F; v.z *= ALPHA_F; v.w *= ALPHA_F;
        ((float4*)h)[idx] = v;
    }
}

// -------------------- hop: one warp per node, lane owns 4 features ----------
__global__ void __launch_bounds__(256)
hop_kernel(const float* __restrict__ xin, float* __restrict__ xout,
           float* __restrict__ h) {
    const int warp = (blockIdx.x * blockDim.x + threadIdx.x) >> 5;
    const int lane = threadIdx.x & 31;
    if (warp >= NN) return;

    const float4* __restrict__ in4 = (const float4*)xin;

    const float dv = g_dinv[warp];
    const float sw = dv * dv;                       // self-loop weight
    float4 xi = in4[warp * 32 + lane];
    float4 acc;
    acc.x = sw * xi.x; acc.y = sw * xi.y; acc.z = sw * xi.z; acc.w = sw * xi.w;

    const int start = g_rowptr[warp];
    const int len   = g_deg[warp] - 1;

    for (int base = 0; base < len; base += 32) {
        int idx = start + base + lane;
        int   c = 0;
        float w = 0.0f;
        if (base + lane < len) { c = g_col[idx]; w = g_wn[idx]; }
        int rem = len - base; if (rem > 32) rem = 32;
        int j = 0;
        for (; j + 4 <= rem; j += 4) {
            int   s0 = __shfl_sync(0xffffffffu, c, j + 0);
            int   s1 = __shfl_sync(0xffffffffu, c, j + 1);
            int   s2 = __shfl_sync(0xffffffffu, c, j + 2);
            int   s3 = __shfl_sync(0xffffffffu, c, j + 3);
            float w0 = __shfl_sync(0xffffffffu, w, j + 0);
            float w1 = __shfl_sync(0xffffffffu, w, j + 1);
            float w2 = __shfl_sync(0xffffffffu, w, j + 2);
            float w3 = __shfl_sync(0xffffffffu, w, j + 3);
            float4 v0 = __ldg(&in4[s0 * 32 + lane]);
            float4 v1 = __ldg(&in4[s1 * 32 + lane]);
            float4 v2 = __ldg(&in4[s2 * 32 + lane]);
            float4 v3 = __ldg(&in4[s3 * 32 + lane]);
            acc.x += w0 * v0.x + w1 * v1.x + w2 * v2.x + w3 * v3.x;
            acc.y += w0 * v0.y + w1 * v1.y + w2 * v2.y + w3 * v3.y;
            acc.z += w0 * v0.z + w1 * v1.z + w2 * v2.z + w3 * v3.z;
            acc.w += w0 * v0.w + w1 * v1.w + w2 * v2.w + w3 * v3.w;
        }
        for (; j < rem; j++) {
            int   s0 = __shfl_sync(0xffffffffu, c, j);
            float w0 = __shfl_sync(0xffffffffu, w, j);
            float4 v0 = __ldg(&in4[s0 * 32 + lane]);
            acc.x += w0 * v0.x; acc.y += w0 * v0.y;
            acc.z += w0 * v0.z; acc.w += w0 * v0.w;
        }
    }

    ((float4*)xout)[warp * 32 + lane] = acc;

    float4 hv = ((float4*)h)[warp * 32 + lane];
    hv.x += CW_F * acc.x; hv.y += CW_F * acc.y;
    hv.z += CW_F * acc.z; hv.w += CW_F * acc.w;
    ((float4*)h)[warp * 32 + lane] = hv;
}

// -------------------- GEMM: out = h @ W^T + bias ----------------------------
#define GEMM_NODES 32
__global__ void __launch_bounds__(128)
gemm_kernel(const float* __restrict__ h, const float* __restrict__ bias,
            float* __restrict__ out) {
    __shared__ float4 sh[GEMM_NODES * 32];      // 16 KB
    const int o = threadIdx.x;                  // output channel

    float w[DD];
    #pragma unroll
    for (int i = 0; i < DD; i++) w[i] = g_Wt[i * DD + o];   // coalesced
    const float b = bias[o];

    const int node0 = blockIdx.x * GEMM_NODES;
    const float4* h4 = (const float4*)(h + node0 * DD);
    for (int t = threadIdx.x; t < GEMM_NODES * 32; t += 128) sh[t] = h4[t];
    __syncthreads();

    for (int nn = 0; nn < GEMM_NODES; nn++) {
        int node = node0 + nn;
        if (node >= NN) break;
        float acc = b;
        #pragma unroll
        for (int i = 0; i < DD; i += 4) {
            float4 hh = sh[nn * 32 + (i >> 2)];
            acc += hh.x * w[i] + hh.y * w[i + 1] + hh.z * w[i + 2] + hh.w * w[i + 3];
        }
        out[node * DD + o] = acc;
    }
}

// -------------------- launch -------------------------------------------------
extern "C" void kernel_launch(void* const* d_in, const int* in_sizes, int n_in,
                              void* d_out, int out_size) {
    const float* x0   = (const float*)d_in[0];        // [N, 128]
    const int*   ei   = (const int*)  d_in[1];        // [2, E]
    const float* W    = (const float*)d_in[2];        // [128, 128]
    const float* bias = (const float*)d_in[3];        // [128]
    const int* src = ei;
    const int* dst = ei + EE;
    float* out = (float*)d_out;

    void *pA, *pB, *ph;
    cudaGetSymbolAddress(&pA, g_xA);
    cudaGetSymbolAddress(&pB, g_xB);
    cudaGetSymbolAddress(&ph, g_h);
    float* xA = (float*)pA;
    float* xB = (float*)pB;
    float* h  = (float*)ph;

    init_deg_kernel<<<(NN + 255) / 256, 256>>>();
    count_deg_kernel<<<2048, 256>>>(dst);
    dinv_kernel<<<(NN + 255) / 256, 256>>>();
    scan_kernel<<<1, 1024>>>();
    scatter_kernel<<<2048, 256>>>(src, dst);
    transpose_w_kernel<<<DD, DD>>>(W);
    hinit_kernel<<<(NN * DD / 4 + 255) / 256, 256>>>(x0, h);

    const float* xin = x0;
    float* xout = xA;
    for (int k = 0; k < KK; k++) {
        hop_kernel<<<(NN + 7) / 8, 256>>>(xin, xout, h);
        xin  = xout;
        xout = (xout == xA) ? xB : xA;
    }

    gemm_kernel<<<(NN + GEMM_NODES - 1) / GEMM_NODES, 128>>>(h, bias, out);
}

// round 3
// speedup vs baseline: 1.2792x; 1.2792x over previous
#include <cuda_runtime.h>
#include <cuda_fp16.h>

#define NN   50000
#define EE   1600000
#define DD   128
#define KK   16
#define ALPHA_F 0.05f
#define CW_F    (0.95f / 16.0f)
#define NPAD 50048
#define NBLK 49            // ceil(NN/1024)

// -------------------- scratch (static device globals; no allocs) ------------
__device__ uint2 g_x16A[NPAD * 32];     // fp16 features, 4 halves per uint2
__device__ uint2 g_x16B[NPAD * 32];
__device__ float g_h [NPAD * DD];       // fp32 accumulator
__device__ int   g_deg[NN];
__device__ float g_dinv[NN];
__device__ int   g_rowptr[NN + 1];
__device__ int   g_cursor[NN];
__device__ int   g_col[EE];
__device__ float g_wn[EE];
__device__ float g_Wt[DD * DD];
__device__ int   g_bsum[NBLK];
__device__ int   g_boff[NBLK];

// -------------------- prep kernels ------------------------------------------
__global__ void init_deg_kernel() {
    int v = blockIdx.x * blockDim.x + threadIdx.x;
    if (v < NN) { g_deg[v] = 1; g_cursor[v] = 0; }
}

__global__ void count_deg_kernel(const int* __restrict__ dst) {
    for (int e = blockIdx.x * blockDim.x + threadIdx.x; e < EE;
         e += gridDim.x * blockDim.x) {
        atomicAdd(&g_deg[dst[e]], 1);
    }
}

__global__ void dinv_kernel() {
    int v = blockIdx.x * blockDim.x + threadIdx.x;
    if (v < NN) g_dinv[v] = rsqrtf((float)g_deg[v]);
}

// inclusive block scan over 1024 threads
__device__ __forceinline__ int block_scan_inc(int v, int tid) {
    __shared__ int ws[32];
    const int lane = tid & 31, wid = tid >> 5;
    int x = v;
    #pragma unroll
    for (int d = 1; d < 32; d <<= 1) {
        int y = __shfl_up_sync(0xffffffffu, x, d);
        if (lane >= d) x += y;
    }
    if (lane == 31) ws[wid] = x;
    __syncthreads();
    if (wid == 0) {
        int s = ws[lane];
        int t = s;
        #pragma unroll
        for (int d = 1; d < 32; d <<= 1) {
            int y = __shfl_up_sync(0xffffffffu, t, d);
            if (lane >= d) t += y;
        }
        ws[lane] = t - s;     // exclusive warp offsets
    }
    __syncthreads();
    return x + ws[wid];
}

// phase 1: per-block sums of (deg-1)
__global__ void scan1_kernel() {
    __shared__ int ws[32];
    int tid = threadIdx.x;
    int i = blockIdx.x * 1024 + tid;
    int v = (i < NN) ? (g_deg[i] - 1) : 0;
    #pragma unroll
    for (int d = 16; d > 0; d >>= 1) v += __shfl_down_sync(0xffffffffu, v, d);
    if ((tid & 31) == 0) ws[tid >> 5] = v;
    __syncthreads();
    if (tid < 32) {
        int s = ws[tid];
        #pragma unroll
        for (int d = 16; d > 0; d >>= 1) s += __shfl_down_sync(0xffffffffu, s, d);
        if (tid == 0) g_bsum[blockIdx.x] = s;
    }
}

// phase 2: exclusive scan of the 49 block sums (1 block)
__global__ void scan2_kernel() {
    int tid = threadIdx.x;
    int v = (tid < NBLK) ? g_bsum[tid] : 0;
    int inc = block_scan_inc(v, tid);
    if (tid < NBLK) g_boff[tid] = inc - v;
    if (tid == 0) g_rowptr[NN] = EE;
}

// phase 3: block-local scan + offset -> exclusive rowptr
__global__ void scan3_kernel() {
    int tid = threadIdx.x;
    int i = blockIdx.x * 1024 + tid;
    int v = (i < NN) ? (g_deg[i] - 1) : 0;
    int inc = block_scan_inc(v, tid);
    if (i < NN) g_rowptr[i] = inc - v + g_boff[blockIdx.x];
}

__global__ void scatter_kernel(const int* __restrict__ src,
                               const int* __restrict__ dst) {
    for (int e = blockIdx.x * blockDim.x + threadIdx.x; e < EE;
         e += gridDim.x * blockDim.x) {
        int s = src[e];
        int d = dst[e];
        int pos = g_rowptr[d] + atomicAdd(&g_cursor[d], 1);
        g_col[pos] = s;
        g_wn[pos]  = g_dinv[s] * g_dinv[d];
    }
}

__global__ void transpose_w_kernel(const float* __restrict__ W) {
    int o = threadIdx.x;
    int i = blockIdx.x;
    g_Wt[i * DD + o] = W[o * DD + i];
}

// h = ALPHA * x0 (fp32), x16 = half(x0)
__global__ void hinit_kernel(const float* __restrict__ x0) {
    int idx = blockIdx.x * blockDim.x + threadIdx.x;    // 4-feature group index
    const int total = NN * 32;
    if (idx >= total) return;
    float4 v = ((const float4*)x0)[idx];
    float4 hv;
    hv.x = ALPHA_F * v.x; hv.y = ALPHA_F * v.y;
    hv.z = ALPHA_F * v.z; hv.w = ALPHA_F * v.w;
    ((float4*)g_h)[idx] = hv;
    __half2 p01 = __floats2half2_rn(v.x, v.y);
    __half2 p23 = __floats2half2_rn(v.z, v.w);
    uint2 o;
    o.x = *(unsigned int*)&p01;
    o.y = *(unsigned int*)&p23;
    g_x16A[idx] = o;
}

// -------------------- hop: one warp per node, lane owns 4 fp16 features -----
__device__ __forceinline__ void acc_edge(float4& acc, uint2 r, float w) {
    __half2 p01 = *(__half2*)&r.x;
    __half2 p23 = *(__half2*)&r.y;
    float2 f01 = __half22float2(p01);
    float2 f23 = __half22float2(p23);
    acc.x += w * f01.x; acc.y += w * f01.y;
    acc.z += w * f23.x; acc.w += w * f23.y;
}

__global__ void __launch_bounds__(256)
hop_kernel(const uint2* __restrict__ xin, uint2* __restrict__ xout,
           float* __restrict__ h) {
    const int warp = (blockIdx.x * blockDim.x + threadIdx.x) >> 5;
    const int lane = threadIdx.x & 31;
    if (warp >= NN) return;

    const float dv = g_dinv[warp];
    const float sw = dv * dv;
    uint2 xr = __ldg(&xin[warp * 32 + lane]);
    float4 acc = {0.f, 0.f, 0.f, 0.f};
    acc_edge(acc, xr, sw);

    const int start = g_rowptr[warp];
    const int len   = g_deg[warp] - 1;

    for (int base = 0; base < len; base += 32) {
        int idx = start + base + lane;
        int   c = 0;
        float w = 0.0f;
        if (base + lane < len) { c = g_col[idx]; w = g_wn[idx]; }
        int rem = len - base; if (rem > 32) rem = 32;
        int j = 0;
        for (; j + 4 <= rem; j += 4) {
            int   s0 = __shfl_sync(0xffffffffu, c, j + 0);
            int   s1 = __shfl_sync(0xffffffffu, c, j + 1);
            int   s2 = __shfl_sync(0xffffffffu, c, j + 2);
            int   s3 = __shfl_sync(0xffffffffu, c, j + 3);
            float w0 = __shfl_sync(0xffffffffu, w, j + 0);
            float w1 = __shfl_sync(0xffffffffu, w, j + 1);
            float w2 = __shfl_sync(0xffffffffu, w, j + 2);
            float w3 = __shfl_sync(0xffffffffu, w, j + 3);
            uint2 v0 = __ldg(&xin[s0 * 32 + lane]);
            uint2 v1 = __ldg(&xin[s1 * 32 + lane]);
            uint2 v2 = __ldg(&xin[s2 * 32 + lane]);
            uint2 v3 = __ldg(&xin[s3 * 32 + lane]);
            acc_edge(acc, v0, w0);
            acc_edge(acc, v1, w1);
            acc_edge(acc, v2, w2);
            acc_edge(acc, v3, w3);
        }
        for (; j < rem; j++) {
            int   s0 = __shfl_sync(0xffffffffu, c, j);
            float w0 = __shfl_sync(0xffffffffu, w, j);
            uint2 v0 = __ldg(&xin[s0 * 32 + lane]);
            acc_edge(acc, v0, w0);
        }
    }

    // write fp16 xout
    __half2 o01 = __floats2half2_rn(acc.x, acc.y);
    __half2 o23 = __floats2half2_rn(acc.z, acc.w);
    uint2 ow;
    ow.x = *(unsigned int*)&o01;
    ow.y = *(unsigned int*)&o23;
    xout[warp * 32 + lane] = ow;

    // fp32 h accumulate
    float4 hv = ((float4*)h)[warp * 32 + lane];
    hv.x += CW_F * acc.x; hv.y += CW_F * acc.y;
    hv.z += CW_F * acc.z; hv.w += CW_F * acc.w;
    ((float4*)h)[warp * 32 + lane] = hv;
}

// -------------------- GEMM: out = h @ W^T + bias ----------------------------
#define GEMM_NODES 32
__global__ void __launch_bounds__(128)
gemm_kernel(const float* __restrict__ h, const float* __restrict__ bias,
            float* __restrict__ out) {
    __shared__ float4 sh[GEMM_NODES * 32];      // 16 KB
    const int o = threadIdx.x;

    float w[DD];
    #pragma unroll
    for (int i = 0; i < DD; i++) w[i] = g_Wt[i * DD + o];
    const float b = bias[o];

    const int node0 = blockIdx.x * GEMM_NODES;
    const float4* h4 = (const float4*)(h + node0 * DD);
    for (int t = threadIdx.x; t < GEMM_NODES * 32; t += 128) sh[t] = h4[t];
    __syncthreads();

    for (int nn = 0; nn < GEMM_NODES; nn++) {
        int node = node0 + nn;
        if (node >= NN) break;
        float acc = b;
        #pragma unroll
        for (int i = 0; i < DD; i += 4) {
            float4 hh = sh[nn * 32 + (i >> 2)];
            acc += hh.x * w[i] + hh.y * w[i + 1] + hh.z * w[i + 2] + hh.w * w[i + 3];
        }
        out[node * DD + o] = acc;
    }
}

// -------------------- launch -------------------------------------------------
extern "C" void kernel_launch(void* const* d_in, const int* in_sizes, int n_in,
                              void* d_out, int out_size) {
    const float* x0   = (const float*)d_in[0];
    const int*   ei   = (const int*)  d_in[1];
    const float* W    = (const float*)d_in[2];
    const float* bias = (const float*)d_in[3];
    const int* src = ei;
    const int* dst = ei + EE;
    float* out = (float*)d_out;

    void *pA, *pB, *ph;
    cudaGetSymbolAddress(&pA, g_x16A);
    cudaGetSymbolAddress(&pB, g_x16B);
    cudaGetSymbolAddress(&ph, g_h);
    uint2* xA = (uint2*)pA;
    uint2* xB = (uint2*)pB;
    float* h  = (float*)ph;

    init_deg_kernel<<<(NN + 255) / 256, 256>>>();
    count_deg_kernel<<<2048, 256>>>(dst);
    dinv_kernel<<<(NN + 255) / 256, 256>>>();
    scan1_kernel<<<NBLK, 1024>>>();
    scan2_kernel<<<1, 1024>>>();
    scan3_kernel<<<NBLK, 1024>>>();
    scatter_kernel<<<2048, 256>>>(src, dst);
    transpose_w_kernel<<<DD, DD>>>(W);
    hinit_kernel<<<(NN * 32 + 255) / 256, 256>>>(x0);

    const uint2* xin = xA;
    uint2* xout = xB;
    for (int k = 0; k < KK; k++) {
        hop_kernel<<<(NN + 7) / 8, 256>>>(xin, xout, h);
        xin  = xout;
        xout = (xout == xB) ? xA : xB;
    }

    gemm_kernel<<<(NN + GEMM_NODES - 1) / GEMM_NODES, 128>>>(h, bias, out);
}